// round 15
// baseline (speedup 1.0000x reference)
#include <cuda_runtime.h>
#include <cstdint>
#include <math.h>

#define NB 4
#define NC 64
#define HW 4096
#define BC (NB*NC)
#define NTILES 32   // 4096 keys / 128

// Scratch (allocation-free rule: __device__ globals)
__device__ float2   g_part[BC*4];         // per (bc, quarter) partial (sum, sumsq)
__device__ uint32_t g_wpk[24*8*64];       // w_qkv packed in tf32 B-frag order
__device__ uint32_t g_wpj[8*8*64];        // w_proj packed in tf32 B-frag order
__device__ uint32_t g_qb[NB*HW*32];       // Q bf16x2 token-major, x(0.125*log2e)
__device__ uint32_t g_kp[NB*NTILES*4096]; // K bf16 packed in m16n8k16 B-frag order
__device__ uint32_t g_vp[NB*NTILES*4096]; // V bf16 packed in m16n8k16 B-frag order
__device__ float    g_po[2*NB*64*HW];     // PROJECTED partial O per key-half: [kh][b][o][n]
__device__ float    g_ls[2*NB*HW];        // partial exp-sum per key-half

// ===========================================================================
// helpers
// ===========================================================================
__device__ __forceinline__ uint32_t smem_u32(const void* p) {
    uint32_t a;
    asm("{ .reg .u64 t; cvta.to.shared.u64 t, %1; cvt.u32.u64 %0, t; }" : "=r"(a) : "l"(p));
    return a;
}
__device__ __forceinline__ uint32_t bf16x2(float lo, float hi) {
    uint32_t r; asm("cvt.rn.bf16x2.f32 %0, %1, %2;" : "=r"(r) : "f"(hi), "f"(lo));
    return r;
}
__device__ __forceinline__ float tf32r(float x) {
    uint32_t u; asm("cvt.rna.tf32.f32 %0, %1;" : "=r"(u) : "f"(x));
    return __uint_as_float(u);
}
__device__ __forceinline__ uint32_t tf32u(float x) {
    uint32_t u; asm("cvt.rna.tf32.f32 %0, %1;" : "=r"(u) : "f"(x));
    return u;
}
__device__ __forceinline__ float ex2f(float x) {
    float r; asm("ex2.approx.f32 %0, %1;" : "=f"(r) : "f"(x));
    return r;
}
__device__ __forceinline__ void cp16(uint32_t dst, const void* src) {
    asm volatile("{ .reg .u64 g; cvta.to.global.u64 g, %1; "
                 "cp.async.cg.shared.global [%0], [g], 16; }"
                 :: "r"(dst), "l"(src) : "memory");
}
__device__ __forceinline__ void cp_commit() {
    asm volatile("cp.async.commit_group;" ::: "memory");
}
__device__ __forceinline__ void mma_bf16(float* d, const uint32_t* a, uint32_t b0, uint32_t b1) {
    asm volatile("mma.sync.aligned.m16n8k16.row.col.f32.bf16.bf16.f32 "
        "{%0,%1,%2,%3}, {%4,%5,%6,%7}, {%8,%9}, {%0,%1,%2,%3};"
        : "+f"(d[0]), "+f"(d[1]), "+f"(d[2]), "+f"(d[3])
        : "r"(a[0]), "r"(a[1]), "r"(a[2]), "r"(a[3]), "r"(b0), "r"(b1));
}
__device__ __forceinline__ void mma_tf32(float* d, const uint32_t* a, uint32_t b0, uint32_t b1) {
    asm volatile("mma.sync.aligned.m16n8k8.row.col.f32.tf32.tf32.f32 "
        "{%0,%1,%2,%3}, {%4,%5,%6,%7}, {%8,%9}, {%0,%1,%2,%3};"
        : "+f"(d[0]), "+f"(d[1]), "+f"(d[2]), "+f"(d[3])
        : "r"(a[0]), "r"(a[1]), "r"(a[2]), "r"(a[3]), "r"(b0), "r"(b1));
}
__device__ __forceinline__ void lds64(uint32_t addr, uint32_t& b0, uint32_t& b1) {
    asm volatile("ld.shared.v2.b32 {%0,%1}, [%2];" : "=r"(b0), "=r"(b1) : "r"(addr));
}

// ===========================================================================
// Kernel 1: instance-norm partial stats + one-time w_qkv / w_proj packs.
// ===========================================================================
__global__ void stats_kernel(const float* __restrict__ x,
                             const float* __restrict__ w_qkv,
                             const float* __restrict__ w_proj) {
    int bx = blockIdx.x;              // bc*4 + quarter
    int bc = bx >> 2, q = bx & 3;
    int t = threadIdx.x;              // 128
    const float4* p = (const float4*)(x + (size_t)bc * HW) + q * 256;
    float4 v1 = p[t], v2 = p[t + 128];
    float s  = v1.x + v1.y + v1.z + v1.w + v2.x + v2.y + v2.z + v2.w;
    float s2 = v1.x*v1.x + v1.y*v1.y + v1.z*v1.z + v1.w*v1.w
             + v2.x*v2.x + v2.y*v2.y + v2.z*v2.z + v2.w*v2.w;
    #pragma unroll
    for (int off = 16; off; off >>= 1) {
        s  += __shfl_xor_sync(0xffffffffu, s,  off);
        s2 += __shfl_xor_sync(0xffffffffu, s2, off);
    }
    __shared__ float sh[4], sh2[4];
    int w = t >> 5;
    if ((t & 31) == 0) { sh[w] = s; sh2[w] = s2; }
    __syncthreads();
    if (t == 0)
        g_part[bx] = make_float2(sh[0]+sh[1]+sh[2]+sh[3], sh2[0]+sh2[1]+sh2[2]+sh2[3]);

    if (bx < 192 && t < 64) {
        int nn24 = bx >> 3, kk = bx & 7;
        int no = t >> 3, ck = (t >> 1) & 3, h = t & 1;
        g_wpk[bx * 64 + t] = tf32u(w_qkv[(nn24*8 + no)*64 + kk*8 + ck + 4*h]);
    } else if (bx >= 192 && bx < 256 && t < 64) {
        int px = bx - 192;
        int nn8 = px >> 3, kk = px & 7;
        int no = t >> 3, ck = (t >> 1) & 3, h = t & 1;
        g_wpj[px * 64 + t] = tf32u(w_proj[(nn8*8 + no)*64 + kk*8 + ck + 4*h]);
    }
}

// ===========================================================================
// Kernel 2: normalize + qkv via tf32 mma.sync; pack Q/K/V bf16 fragments.
// ===========================================================================
#define QKV2_BIAS 0        // 192 floats
#define QKV2_MS   768      // mean[64], rstd[64]
#define QKV2_HS   1280     // [64][68] floats
#define QKV2_WPK  18688    // 48KB packed w
#define QKV2_ST   67840    // [192][65] floats
#define QKV2_SMEM 117760

__global__ __launch_bounds__(256, 1) void qkv_kernel(const float* __restrict__ x,
                           const float* __restrict__ b_qkv) {
    extern __shared__ __align__(16) char smem[];
    float* bias  = (float*)(smem + QKV2_BIAS);
    float* smean = (float*)(smem + QKV2_MS);
    float* srstd = smean + 64;
    float* hs    = (float*)(smem + QKV2_HS);   // stride 68
    float* st    = (float*)(smem + QKV2_ST);   // stride 65
    uint32_t sb = smem_u32(smem);
    int b  = blockIdx.y;
    int n0 = blockIdx.x << 6;
    int t = threadIdx.x;

    #pragma unroll
    for (int j = 0; j < 12; j++)
        cp16(sb + QKV2_WPK + t * 16 + j * 4096, (const char*)g_wpk + t * 16 + j * 4096);
    cp_commit();

    if (t < 48) ((float4*)bias)[t] = ((const float4*)b_qkv)[t];
    if (t < 64) {
        float s = 0.f, s2 = 0.f;
        #pragma unroll
        for (int q = 0; q < 4; q++) {
            float2 pp = g_part[(b * 64 + t) * 4 + q];
            s += pp.x; s2 += pp.y;
        }
        float m = s * (1.f / HW);
        float var = s2 * (1.f / HW) - m * m;
        smean[t] = m;
        srstd[t] = rsqrtf(var + 1e-5f);
    }
    __syncthreads();

    for (int i = t; i < 1024; i += 256) {
        int c = i >> 4, v4 = i & 15;
        float4 xv = ((const float4*)(x + ((size_t)(b * 64 + c) << 12) + n0))[v4];
        float m = smean[c], r = srstd[c];
        float* row = hs + c * 68 + v4 * 4;
        row[0] = tf32r((xv.x - m) * r); row[1] = tf32r((xv.y - m) * r);
        row[2] = tf32r((xv.z - m) * r); row[3] = tf32r((xv.w - m) * r);
    }
    asm volatile("cp.async.wait_group 0;" ::: "memory");
    __syncthreads();

    {
        int w = t >> 5, l = t & 31, g = l >> 2, tig = l & 3;
        int mt = w & 3, nh = w >> 2;
        int nbase = mt * 16 + g;
        const uint32_t* hsu = (const uint32_t*)hs;

        uint32_t af[8][4];
        #pragma unroll
        for (int kk = 0; kk < 8; kk++) {
            int c0 = kk * 8 + tig;
            af[kk][0] = hsu[c0 * 68 + nbase];
            af[kk][1] = hsu[c0 * 68 + nbase + 8];
            af[kk][2] = hsu[(c0 + 4) * 68 + nbase];
            af[kk][3] = hsu[(c0 + 4) * 68 + nbase + 8];
        }

        #pragma unroll
        for (int nn = 0; nn < 12; nn++) {
            float acc[4] = {0.f, 0.f, 0.f, 0.f};
            uint32_t wb = sb + QKV2_WPK + (uint32_t)((nh * 12 + nn) * 8) * 256;
            #pragma unroll
            for (int kk = 0; kk < 8; kk++) {
                uint32_t b0, b1;
                lds64(wb + kk * 256 + l * 8, b0, b1);
                mma_tf32(acc, af[kk], b0, b1);
            }
            int o = nh * 96 + nn * 8 + 2 * tig;
            float b0f = bias[o], b1f = bias[o + 1];
            st[o * 65 + nbase]           = acc[0] + b0f;
            st[(o + 1) * 65 + nbase]     = acc[1] + b1f;
            st[o * 65 + nbase + 8]       = acc[2] + b0f;
            st[(o + 1) * 65 + nbase + 8] = acc[3] + b1f;
        }
    }
    __syncthreads();

    int tile = n0 >> 7;
    int kb0  = n0 & 64;
    size_t tbase = (size_t)(b * 32 + tile) * 4096;

    const float QS = 0.125f * 1.4426950408889634f;   // fold attn scale + log2(e)
    for (int i = t; i < 2048; i += 256) {
        int n = i >> 5, c2 = i & 31;
        float lo = st[(2*c2  ) * 65 + n] * QS;
        float hi = st[(2*c2+1) * 65 + n] * QS;
        g_qb[((size_t)b * HW + n0 + n) * 32 + c2] = bf16x2(lo, hi);
    }
    for (int i = t; i < 2048; i += 256) {
        int nn_l = i >> 8, kk = (i >> 6) & 3, g = (i >> 3) & 7, tig = (i >> 1) & 3, reg = i & 1;
        int n_l = nn_l * 8 + g;
        int c = kk * 16 + reg * 8 + tig * 2;
        float lo = st[(64 + c    ) * 65 + n_l];
        float hi = st[(64 + c + 1) * 65 + n_l];
        int nn_abs = (kb0 >> 3) + nn_l;
        g_kp[tbase + (nn_abs * 4 + kk) * 64 + g * 8 + tig * 2 + reg] = bf16x2(lo, hi);
    }
    for (int i = t; i < 2048; i += 256) {
        int nn = i >> 8, kk_l = (i >> 6) & 3, g = (i >> 3) & 7, tig = (i >> 1) & 3, reg = i & 1;
        int c = nn * 8 + g;
        int n_l = kk_l * 16 + reg * 8 + tig * 2;
        float lo = st[(128 + c) * 65 + n_l    ];
        float hi = st[(128 + c) * 65 + n_l + 1];
        int kk_abs = (kb0 >> 4) + kk_l;
        g_vp[tbase + (nn * 8 + kk_abs) * 64 + g * 8 + tig * 2 + reg] = bf16x2(lo, hi);
    }
}

// ===========================================================================
// Kernel 3: bf16 flash attention, split-K over keys + FUSED tf32 projection
// of the (unnormalized) partial O.  Writes projected partials [kh][b][o][n].
// CTA = (256 q-rows, key-half, batch): 256 threads, 8 warps x M=32.
// ===========================================================================
#define EP_WPJ   69632                 // packed w_proj (16KB) after Os [256][68]
#define SMEM_ATT (EP_WPJ + 16384)      // 86016

__device__ __forceinline__ void stage_tile(uint32_t sb, int b, int tile, int buf, int t) {
    const char* ks = (const char*)g_kp + (((size_t)b * NTILES + tile) << 14);
    const char* vs = (const char*)g_vp + (((size_t)b * NTILES + tile) << 14);
    uint32_t kd = sb + ((uint32_t)buf << 14);
    uint32_t vd = sb + 32768u + ((uint32_t)buf << 14);
    #pragma unroll
    for (int j = 0; j < 4; j++) {
        cp16(kd + t * 16 + j * 4096, ks + t * 16 + j * 4096);
        cp16(vd + t * 16 + j * 4096, vs + t * 16 + j * 4096);
    }
}

__global__ __launch_bounds__(256, 1) void attn_mma_kernel() {
    extern __shared__ __align__(128) char smem[];
    uint32_t sb = smem_u32(smem);
    const int t = threadIdx.x, w = t >> 5, l = t & 31;
    const int b = blockIdx.y;
    const int q0 = (blockIdx.x >> 1) << 8;     // 256-query tile
    const int kh = blockIdx.x & 1;             // key half
    const int g = l >> 2, tig = l & 3;
    const int t0 = kh * 16;

    uint32_t qf[2][4][4];
    #pragma unroll
    for (int mt = 0; mt < 2; mt++) {
        const uint32_t* Qb = g_qb + ((size_t)b * HW + q0 + w * 32 + mt * 16) * 32;
        #pragma unroll
        for (int kk = 0; kk < 4; kk++) {
            qf[mt][kk][0] = Qb[(size_t)g       * 32 + 8*kk + tig];
            qf[mt][kk][1] = Qb[(size_t)(g + 8) * 32 + 8*kk + tig];
            qf[mt][kk][2] = Qb[(size_t)g       * 32 + 8*kk + tig + 4];
            qf[mt][kk][3] = Qb[(size_t)(g + 8) * 32 + 8*kk + tig + 4];
        }
    }

    stage_tile(sb, b, t0, 0, t); cp_commit();
    stage_tile(sb, b, t0 + 1, 1, t); cp_commit();

    float ls[2][2] = {{0.f, 0.f}, {0.f, 0.f}};
    float of[2][8][4];
    #pragma unroll
    for (int mt = 0; mt < 2; mt++)
        #pragma unroll
        for (int nn = 0; nn < 8; nn++)
            #pragma unroll
            for (int j = 0; j < 4; j++) of[mt][nn][j] = 0.f;

    for (int i = 0; i < 16; i++) {
        int buf = i & 1;
        if (i < 14) asm volatile("cp.async.wait_group 1;" ::: "memory");
        else        asm volatile("cp.async.wait_group 0;" ::: "memory");
        __syncthreads();

        uint32_t kb = sb + ((uint32_t)buf << 14);
        uint32_t vb = sb + 32768u + ((uint32_t)buf << 14);

        #pragma unroll
        for (int h = 0; h < 2; h++) {
            float sf[2][8][4];
            #pragma unroll
            for (int nn_l = 0; nn_l < 8; nn_l++) {
                #pragma unroll
                for (int mt = 0; mt < 2; mt++) {
                    sf[mt][nn_l][0] = 0.f; sf[mt][nn_l][1] = 0.f;
                    sf[mt][nn_l][2] = 0.f; sf[mt][nn_l][3] = 0.f;
                }
                int nn = 8 * h + nn_l;
                #pragma unroll
                for (int kk = 0; kk < 4; kk++) {
                    uint32_t b0, b1;
                    lds64(kb + ((uint32_t)(nn * 4 + kk) << 8) + ((uint32_t)l << 3), b0, b1);
                    mma_bf16(sf[0][nn_l], qf[0][kk], b0, b1);
                    mma_bf16(sf[1][nn_l], qf[1][kk], b0, b1);
                }
            }

            #pragma unroll
            for (int mt = 0; mt < 2; mt++) {
                float s0 = 0.f, s1 = 0.f;
                #pragma unroll
                for (int nn = 0; nn < 8; nn++) {
                    sf[mt][nn][0] = ex2f(sf[mt][nn][0]);
                    sf[mt][nn][1] = ex2f(sf[mt][nn][1]);
                    sf[mt][nn][2] = ex2f(sf[mt][nn][2]);
                    sf[mt][nn][3] = ex2f(sf[mt][nn][3]);
                    s0 += sf[mt][nn][0] + sf[mt][nn][1];
                    s1 += sf[mt][nn][2] + sf[mt][nn][3];
                }
                ls[mt][0] += s0;
                ls[mt][1] += s1;
            }

            uint32_t pf[2][4][4];
            #pragma unroll
            for (int mt = 0; mt < 2; mt++)
                #pragma unroll
                for (int m = 0; m < 4; m++) {
                    pf[mt][m][0] = bf16x2(sf[mt][2*m  ][0], sf[mt][2*m  ][1]);
                    pf[mt][m][1] = bf16x2(sf[mt][2*m  ][2], sf[mt][2*m  ][3]);
                    pf[mt][m][2] = bf16x2(sf[mt][2*m+1][0], sf[mt][2*m+1][1]);
                    pf[mt][m][3] = bf16x2(sf[mt][2*m+1][2], sf[mt][2*m+1][3]);
                }

            #pragma unroll
            for (int nn = 0; nn < 8; nn++) {
                #pragma unroll
                for (int kk_l = 0; kk_l < 4; kk_l++) {
                    int kk = 4 * h + kk_l;
                    uint32_t b0, b1;
                    lds64(vb + ((uint32_t)(nn * 8 + kk) << 8) + ((uint32_t)l << 3), b0, b1);
                    mma_bf16(of[0][nn], pf[0][kk_l], b0, b1);
                    mma_bf16(of[1][nn], pf[1][kk_l], b0, b1);
                }
            }
        }

        __syncthreads();
        if (i + 2 < 16) { stage_tile(sb, b, t0 + i + 2, buf, t); cp_commit(); }
    }

    // ---- exp-sum reduction + store ----
    #pragma unroll
    for (int mt = 0; mt < 2; mt++) {
        ls[mt][0] += __shfl_xor_sync(0xffffffffu, ls[mt][0], 1);
        ls[mt][0] += __shfl_xor_sync(0xffffffffu, ls[mt][0], 2);
        ls[mt][1] += __shfl_xor_sync(0xffffffffu, ls[mt][1], 1);
        ls[mt][1] += __shfl_xor_sync(0xffffffffu, ls[mt][1], 2);
        if (tig == 0) {
            size_t lbase = (size_t)(kh * NB + b) * HW + q0 + w * 32 + mt * 16;
            g_ls[lbase + g]     = ls[mt][0];
            g_ls[lbase + g + 8] = ls[mt][1];
        }
    }

    // ========================================================================
    // Fused epilogue: project UNNORMALIZED partial O with tf32 mma.
    // Os [256][68] <- of (tf32-rounded); w_proj staged; C-frags -> st [64][268]
    // -> coalesced write to g_po[kh][b][o][n].
    // ========================================================================
    __syncthreads();   // mainloop smem dead
    #pragma unroll
    for (int j = 0; j < 4; j++)
        cp16(sb + EP_WPJ + t * 16 + j * 4096, (const char*)g_wpj + t * 16 + j * 4096);
    cp_commit();

    float* Os = (float*)smem;   // [256][68]
    #pragma unroll
    for (int mt = 0; mt < 2; mt++) {
        int row0 = w * 32 + mt * 16 + g;
        #pragma unroll
        for (int nn = 0; nn < 8; nn++) {
            int col = nn * 8 + 2 * tig;
            *(float2*)(Os + row0 * 68 + col) =
                make_float2(tf32r(of[mt][nn][0]), tf32r(of[mt][nn][1]));
            *(float2*)(Os + (row0 + 8) * 68 + col) =
                make_float2(tf32r(of[mt][nn][2]), tf32r(of[mt][nn][3]));
        }
    }
    asm volatile("cp.async.wait_group 0;" ::: "memory");
    __syncthreads();

    float acc[2][8][4];
    {
        const uint32_t* Osu = (const uint32_t*)Os;
        #pragma unroll
        for (int mt = 0; mt < 2; mt++) {
            int nbase = w * 32 + mt * 16 + g;
            uint32_t af[8][4];
            #pragma unroll
            for (int kk = 0; kk < 8; kk++) {
                int c0 = kk * 8 + tig;
                af[kk][0] = Osu[(size_t)nbase * 68 + c0];
                af[kk][1] = Osu[(size_t)(nbase + 8) * 68 + c0];
                af[kk][2] = Osu[(size_t)nbase * 68 + c0 + 4];
                af[kk][3] = Osu[(size_t)(nbase + 8) * 68 + c0 + 4];
            }
            #pragma unroll
            for (int nn = 0; nn < 8; nn++) {
                acc[mt][nn][0] = 0.f; acc[mt][nn][1] = 0.f;
                acc[mt][nn][2] = 0.f; acc[mt][nn][3] = 0.f;
                uint32_t wb = sb + EP_WPJ + (uint32_t)(nn * 8) * 256;
                #pragma unroll
                for (int kk = 0; kk < 8; kk++) {
                    uint32_t b0, b1;
                    lds64(wb + kk * 256 + l * 8, b0, b1);
                    mma_tf32(acc[mt][nn], af[kk], b0, b1);
                }
            }
        }
    }
    __syncthreads();   // Os fully consumed

    float* st = (float*)smem;   // [64][268]
    #pragma unroll
    for (int mt = 0; mt < 2; mt++) {
        int nbase = w * 32 + mt * 16 + g;
        #pragma unroll
        for (int nn = 0; nn < 8; nn++) {
            int o = nn * 8 + 2 * tig;
            st[o * 268 + nbase]           = acc[mt][nn][0];
            st[(o + 1) * 268 + nbase]     = acc[mt][nn][1];
            st[o * 268 + nbase + 8]       = acc[mt][nn][2];
            st[(o + 1) * 268 + nbase + 8] = acc[mt][nn][3];
        }
    }
    __syncthreads();

    // coalesced write: 64 o-rows x 256 tokens
    for (int i = t; i < 4096; i += 256) {
        int o = i >> 6, f4 = i & 63;
        float4 v = *(const float4*)(st + o * 268 + f4 * 4);
        *(float4*)(g_po + (((size_t)(kh * NB + b) * 64 + o) << 12) + q0 + f4 * 4) = v;
    }
}

// ===========================================================================
// Kernel 4: elementwise merge: out = x + bias[o] + (p0+p1) * (1/(l0+l1)).
// Grid (64, NB) = 256 blocks, 256 threads; block covers 64 tokens x 64 o
// = 4096 floats = 1024 float4 -> 4 iterations of 256 threads.
// ===========================================================================
__global__ __launch_bounds__(256) void merge_kernel(
        const float* __restrict__ x,
        const float* __restrict__ b_proj,
        float* __restrict__ out) {
    __shared__ float lsinv[64];
    __shared__ float bias_s[64];
    int b  = blockIdx.y;
    int n0 = blockIdx.x << 6;
    int t = threadIdx.x;

    if (t < 64) {
        lsinv[t] = __fdividef(1.f, g_ls[(size_t)b * HW + n0 + t] +
                                   g_ls[(size_t)(NB + b) * HW + n0 + t]);
        bias_s[t] = b_proj[t];
    }
    __syncthreads();

    #pragma unroll
    for (int j = 0; j < 4; j++) {
        int idx = j * 256 + t;           // 0..1023 float4s
        int o = idx >> 4, f4 = idx & 15; // o < 64, 16 float4 per 64-token row
        size_t e0 = (((size_t)(b * 64 + o)) << 12) + n0 + f4 * 4;
        float4 a  = *(const float4*)(g_po + e0);
        float4 c  = *(const float4*)(g_po + (((size_t)(NB * 64) << 12)) + e0);
        float4 xv = *(const float4*)(x + e0);
        int nb4 = f4 * 4;
        float bias = bias_s[o];
        float4 r;
        r.x = xv.x + bias + (a.x + c.x) * lsinv[nb4    ];
        r.y = xv.y + bias + (a.y + c.y) * lsinv[nb4 + 1];
        r.z = xv.z + bias + (a.z + c.z) * lsinv[nb4 + 2];
        r.w = xv.w + bias + (a.w + c.w) * lsinv[nb4 + 3];
        *(float4*)(out + e0) = r;
    }
}

// ===========================================================================
extern "C" void kernel_launch(void* const* d_in, const int* in_sizes, int n_in,
                              void* d_out, int out_size) {
    const float* x      = (const float*)d_in[0];
    const float* w_qkv  = (const float*)d_in[1];
    const float* b_qkv  = (const float*)d_in[2];
    const float* w_proj = (const float*)d_in[3];
    const float* b_proj = (const float*)d_in[4];
    float* out = (float*)d_out;

    cudaFuncSetAttribute(qkv_kernel,
                         cudaFuncAttributeMaxDynamicSharedMemorySize, QKV2_SMEM);
    cudaFuncSetAttribute(attn_mma_kernel,
                         cudaFuncAttributeMaxDynamicSharedMemorySize, SMEM_ATT);

    stats_kernel<<<BC*4, 128>>>(x, w_qkv, w_proj);
    qkv_kernel<<<dim3(64, NB), 256, QKV2_SMEM>>>(x, b_qkv);
    attn_mma_kernel<<<dim3(32, NB), 256, SMEM_ATT>>>();
    merge_kernel<<<dim3(64, NB), 256>>>(x, b_proj, out);
}

// round 17
// speedup vs baseline: 1.0352x; 1.0352x over previous
#include <cuda_runtime.h>
#include <cstdint>
#include <math.h>

#define NB 4
#define NC 64
#define HW 4096
#define BC (NB*NC)
#define NTILES 32   // 4096 keys / 128

// Scratch (allocation-free rule: __device__ globals)
__device__ float2   g_part[BC*4];         // per (bc, quarter) partial (sum, sumsq)
__device__ uint32_t g_wpk[24*8*64];       // w_qkv packed in tf32 B-frag order
__device__ uint32_t g_wpjb[8*4*64];       // w_proj packed in bf16 m16n8k16 B-frag order
__device__ uint32_t g_qb[NB*HW*32];       // Q bf16x2 token-major, x(0.125*log2e)
__device__ uint32_t g_kp[NB*NTILES*4096]; // K bf16 packed in m16n8k16 B-frag order
__device__ uint32_t g_vp[NB*NTILES*4096]; // V bf16 packed in m16n8k16 B-frag order
__device__ float    g_po[2*NB*64*HW];     // PROJECTED partial O per key-half: [kh][b][o][n]
__device__ float    g_ls[2*NB*HW];        // partial exp-sum per key-half

// ===========================================================================
// helpers
// ===========================================================================
__device__ __forceinline__ uint32_t smem_u32(const void* p) {
    uint32_t a;
    asm("{ .reg .u64 t; cvta.to.shared.u64 t, %1; cvt.u32.u64 %0, t; }" : "=r"(a) : "l"(p));
    return a;
}
__device__ __forceinline__ uint32_t bf16x2(float lo, float hi) {
    uint32_t r; asm("cvt.rn.bf16x2.f32 %0, %1, %2;" : "=r"(r) : "f"(hi), "f"(lo));
    return r;
}
__device__ __forceinline__ float tf32r(float x) {
    uint32_t u; asm("cvt.rna.tf32.f32 %0, %1;" : "=r"(u) : "f"(x));
    return __uint_as_float(u);
}
__device__ __forceinline__ uint32_t tf32u(float x) {
    uint32_t u; asm("cvt.rna.tf32.f32 %0, %1;" : "=r"(u) : "f"(x));
    return u;
}
__device__ __forceinline__ float ex2f(float x) {
    float r; asm("ex2.approx.f32 %0, %1;" : "=f"(r) : "f"(x));
    return r;
}
__device__ __forceinline__ void cp16(uint32_t dst, const void* src) {
    asm volatile("{ .reg .u64 g; cvta.to.global.u64 g, %1; "
                 "cp.async.cg.shared.global [%0], [g], 16; }"
                 :: "r"(dst), "l"(src) : "memory");
}
__device__ __forceinline__ void cp_commit() {
    asm volatile("cp.async.commit_group;" ::: "memory");
}
__device__ __forceinline__ void mma_bf16(float* d, const uint32_t* a, uint32_t b0, uint32_t b1) {
    asm volatile("mma.sync.aligned.m16n8k16.row.col.f32.bf16.bf16.f32 "
        "{%0,%1,%2,%3}, {%4,%5,%6,%7}, {%8,%9}, {%0,%1,%2,%3};"
        : "+f"(d[0]), "+f"(d[1]), "+f"(d[2]), "+f"(d[3])
        : "r"(a[0]), "r"(a[1]), "r"(a[2]), "r"(a[3]), "r"(b0), "r"(b1));
}
__device__ __forceinline__ void mma_tf32(float* d, const uint32_t* a, uint32_t b0, uint32_t b1) {
    asm volatile("mma.sync.aligned.m16n8k8.row.col.f32.tf32.tf32.f32 "
        "{%0,%1,%2,%3}, {%4,%5,%6,%7}, {%8,%9}, {%0,%1,%2,%3};"
        : "+f"(d[0]), "+f"(d[1]), "+f"(d[2]), "+f"(d[3])
        : "r"(a[0]), "r"(a[1]), "r"(a[2]), "r"(a[3]), "r"(b0), "r"(b1));
}
__device__ __forceinline__ void lds64(uint32_t addr, uint32_t& b0, uint32_t& b1) {
    asm volatile("ld.shared.v2.b32 {%0,%1}, [%2];" : "=r"(b0), "=r"(b1) : "r"(addr));
}

// ===========================================================================
// Kernel 1: instance-norm partial stats + one-time w_qkv / w_proj packs.
// ===========================================================================
__global__ void stats_kernel(const float* __restrict__ x,
                             const float* __restrict__ w_qkv,
                             const float* __restrict__ w_proj) {
    int bx = blockIdx.x;              // bc*4 + quarter
    int bc = bx >> 2, q = bx & 3;
    int t = threadIdx.x;              // 128
    const float4* p = (const float4*)(x + (size_t)bc * HW) + q * 256;
    float4 v1 = p[t], v2 = p[t + 128];
    float s  = v1.x + v1.y + v1.z + v1.w + v2.x + v2.y + v2.z + v2.w;
    float s2 = v1.x*v1.x + v1.y*v1.y + v1.z*v1.z + v1.w*v1.w
             + v2.x*v2.x + v2.y*v2.y + v2.z*v2.z + v2.w*v2.w;
    #pragma unroll
    for (int off = 16; off; off >>= 1) {
        s  += __shfl_xor_sync(0xffffffffu, s,  off);
        s2 += __shfl_xor_sync(0xffffffffu, s2, off);
    }
    __shared__ float sh[4], sh2[4];
    int w = t >> 5;
    if ((t & 31) == 0) { sh[w] = s; sh2[w] = s2; }
    __syncthreads();
    if (t == 0)
        g_part[bx] = make_float2(sh[0]+sh[1]+sh[2]+sh[3], sh2[0]+sh2[1]+sh2[2]+sh2[3]);

    if (bx < 192 && t < 64) {
        int nn24 = bx >> 3, kk = bx & 7;
        int no = t >> 3, ck = (t >> 1) & 3, h = t & 1;
        g_wpk[bx * 64 + t] = tf32u(w_qkv[(nn24*8 + no)*64 + kk*8 + ck + 4*h]);
    } else if (bx >= 192 && bx < 224 && t < 64) {
        // w_proj bf16 B-frag pack (mirrors the verified K pack: o<->row, c<->K dim)
        int px = bx - 192;               // 0..31  = nn*4 + kk
        int nn = px >> 2, kk = px & 3;
        int g = t >> 3, tig = (t >> 1) & 3, reg = t & 1;
        int o = nn * 8 + g;
        int c = kk * 16 + reg * 8 + tig * 2;
        g_wpjb[px * 64 + t] = bf16x2(w_proj[o * 64 + c], w_proj[o * 64 + c + 1]);
    }
}

// ===========================================================================
// Kernel 2: normalize + qkv via tf32 mma.sync; pack Q/K/V bf16 fragments.
// ===========================================================================
#define QKV2_BIAS 0        // 192 floats
#define QKV2_MS   768      // mean[64], rstd[64]
#define QKV2_HS   1280     // [64][68] floats
#define QKV2_WPK  18688    // 48KB packed w
#define QKV2_ST   67840    // [192][65] floats
#define QKV2_SMEM 117760

__global__ __launch_bounds__(256, 1) void qkv_kernel(const float* __restrict__ x,
                           const float* __restrict__ b_qkv) {
    extern __shared__ __align__(16) char smem[];
    float* bias  = (float*)(smem + QKV2_BIAS);
    float* smean = (float*)(smem + QKV2_MS);
    float* srstd = smean + 64;
    float* hs    = (float*)(smem + QKV2_HS);   // stride 68
    float* st    = (float*)(smem + QKV2_ST);   // stride 65
    uint32_t sb = smem_u32(smem);
    int b  = blockIdx.y;
    int n0 = blockIdx.x << 6;
    int t = threadIdx.x;

    #pragma unroll
    for (int j = 0; j < 12; j++)
        cp16(sb + QKV2_WPK + t * 16 + j * 4096, (const char*)g_wpk + t * 16 + j * 4096);
    cp_commit();

    if (t < 48) ((float4*)bias)[t] = ((const float4*)b_qkv)[t];
    if (t < 64) {
        float s = 0.f, s2 = 0.f;
        #pragma unroll
        for (int q = 0; q < 4; q++) {
            float2 pp = g_part[(b * 64 + t) * 4 + q];
            s += pp.x; s2 += pp.y;
        }
        float m = s * (1.f / HW);
        float var = s2 * (1.f / HW) - m * m;
        smean[t] = m;
        srstd[t] = rsqrtf(var + 1e-5f);
    }
    __syncthreads();

    for (int i = t; i < 1024; i += 256) {
        int c = i >> 4, v4 = i & 15;
        float4 xv = ((const float4*)(x + ((size_t)(b * 64 + c) << 12) + n0))[v4];
        float m = smean[c], r = srstd[c];
        float* row = hs + c * 68 + v4 * 4;
        row[0] = tf32r((xv.x - m) * r); row[1] = tf32r((xv.y - m) * r);
        row[2] = tf32r((xv.z - m) * r); row[3] = tf32r((xv.w - m) * r);
    }
    asm volatile("cp.async.wait_group 0;" ::: "memory");
    __syncthreads();

    {
        int w = t >> 5, l = t & 31, g = l >> 2, tig = l & 3;
        int mt = w & 3, nh = w >> 2;
        int nbase = mt * 16 + g;
        const uint32_t* hsu = (const uint32_t*)hs;

        uint32_t af[8][4];
        #pragma unroll
        for (int kk = 0; kk < 8; kk++) {
            int c0 = kk * 8 + tig;
            af[kk][0] = hsu[c0 * 68 + nbase];
            af[kk][1] = hsu[c0 * 68 + nbase + 8];
            af[kk][2] = hsu[(c0 + 4) * 68 + nbase];
            af[kk][3] = hsu[(c0 + 4) * 68 + nbase + 8];
        }

        #pragma unroll
        for (int nn = 0; nn < 12; nn++) {
            float acc[4] = {0.f, 0.f, 0.f, 0.f};
            uint32_t wb = sb + QKV2_WPK + (uint32_t)((nh * 12 + nn) * 8) * 256;
            #pragma unroll
            for (int kk = 0; kk < 8; kk++) {
                uint32_t b0, b1;
                lds64(wb + kk * 256 + l * 8, b0, b1);
                mma_tf32(acc, af[kk], b0, b1);
            }
            int o = nh * 96 + nn * 8 + 2 * tig;
            float b0f = bias[o], b1f = bias[o + 1];
            st[o * 65 + nbase]           = acc[0] + b0f;
            st[(o + 1) * 65 + nbase]     = acc[1] + b1f;
            st[o * 65 + nbase + 8]       = acc[2] + b0f;
            st[(o + 1) * 65 + nbase + 8] = acc[3] + b1f;
        }
    }
    __syncthreads();

    int tile = n0 >> 7;
    int kb0  = n0 & 64;
    size_t tbase = (size_t)(b * 32 + tile) * 4096;

    const float QS = 0.125f * 1.4426950408889634f;   // fold attn scale + log2(e)
    for (int i = t; i < 2048; i += 256) {
        int n = i >> 5, c2 = i & 31;
        float lo = st[(2*c2  ) * 65 + n] * QS;
        float hi = st[(2*c2+1) * 65 + n] * QS;
        g_qb[((size_t)b * HW + n0 + n) * 32 + c2] = bf16x2(lo, hi);
    }
    for (int i = t; i < 2048; i += 256) {
        int nn_l = i >> 8, kk = (i >> 6) & 3, g = (i >> 3) & 7, tig = (i >> 1) & 3, reg = i & 1;
        int n_l = nn_l * 8 + g;
        int c = kk * 16 + reg * 8 + tig * 2;
        float lo = st[(64 + c    ) * 65 + n_l];
        float hi = st[(64 + c + 1) * 65 + n_l];
        int nn_abs = (kb0 >> 3) + nn_l;
        g_kp[tbase + (nn_abs * 4 + kk) * 64 + g * 8 + tig * 2 + reg] = bf16x2(lo, hi);
    }
    for (int i = t; i < 2048; i += 256) {
        int nn = i >> 8, kk_l = (i >> 6) & 3, g = (i >> 3) & 7, tig = (i >> 1) & 3, reg = i & 1;
        int c = nn * 8 + g;
        int n_l = kk_l * 16 + reg * 8 + tig * 2;
        float lo = st[(128 + c) * 65 + n_l    ];
        float hi = st[(128 + c) * 65 + n_l + 1];
        int kk_abs = (kb0 >> 4) + kk_l;
        g_vp[tbase + (nn * 8 + kk_abs) * 64 + g * 8 + tig * 2 + reg] = bf16x2(lo, hi);
    }
}

// ===========================================================================
// Kernel 3: bf16 flash attention, split-K over keys + FUSED bf16 projection
// (C-frag of O feeds projection A-frag directly, zero smem staging).
// CTA = (256 q-rows, key-half, batch): 256 threads, 8 warps x M=32.
// smem map: [0,65536) K/V double buffers, reused by st [64][268] (<=68608);
//           [69632,77824) bf16 w_proj pack (safely past st).
// ===========================================================================
#define EP_WPJ   69632
#define SMEM_ATT (EP_WPJ + 8192)       // 77824

__device__ __forceinline__ void stage_tile(uint32_t sb, int b, int tile, int buf, int t) {
    const char* ks = (const char*)g_kp + (((size_t)b * NTILES + tile) << 14);
    const char* vs = (const char*)g_vp + (((size_t)b * NTILES + tile) << 14);
    uint32_t kd = sb + ((uint32_t)buf << 14);
    uint32_t vd = sb + 32768u + ((uint32_t)buf << 14);
    #pragma unroll
    for (int j = 0; j < 4; j++) {
        cp16(kd + t * 16 + j * 4096, ks + t * 16 + j * 4096);
        cp16(vd + t * 16 + j * 4096, vs + t * 16 + j * 4096);
    }
}

__global__ __launch_bounds__(256, 1) void attn_mma_kernel() {
    extern __shared__ __align__(128) char smem[];
    uint32_t sb = smem_u32(smem);
    const int t = threadIdx.x, w = t >> 5, l = t & 31;
    const int b = blockIdx.y;
    const int q0 = (blockIdx.x >> 1) << 8;     // 256-query tile
    const int kh = blockIdx.x & 1;             // key half
    const int g = l >> 2, tig = l & 3;
    const int t0 = kh * 16;

    // stage w_proj pack up-front (own group; drained by mainloop's wait_group 0)
    cp16(sb + EP_WPJ + t * 16, (const char*)g_wpjb + t * 16);
    cp16(sb + EP_WPJ + t * 16 + 4096, (const char*)g_wpjb + t * 16 + 4096);
    cp_commit();

    uint32_t qf[2][4][4];
    #pragma unroll
    for (int mt = 0; mt < 2; mt++) {
        const uint32_t* Qb = g_qb + ((size_t)b * HW + q0 + w * 32 + mt * 16) * 32;
        #pragma unroll
        for (int kk = 0; kk < 4; kk++) {
            qf[mt][kk][0] = Qb[(size_t)g       * 32 + 8*kk + tig];
            qf[mt][kk][1] = Qb[(size_t)(g + 8) * 32 + 8*kk + tig];
            qf[mt][kk][2] = Qb[(size_t)g       * 32 + 8*kk + tig + 4];
            qf[mt][kk][3] = Qb[(size_t)(g + 8) * 32 + 8*kk + tig + 4];
        }
    }

    stage_tile(sb, b, t0, 0, t); cp_commit();
    stage_tile(sb, b, t0 + 1, 1, t); cp_commit();

    float ls[2][2] = {{0.f, 0.f}, {0.f, 0.f}};
    float of[2][8][4];
    #pragma unroll
    for (int mt = 0; mt < 2; mt++)
        #pragma unroll
        for (int nn = 0; nn < 8; nn++)
            #pragma unroll
            for (int j = 0; j < 4; j++) of[mt][nn][j] = 0.f;

    for (int i = 0; i < 16; i++) {
        int buf = i & 1;
        if (i < 14) asm volatile("cp.async.wait_group 1;" ::: "memory");
        else        asm volatile("cp.async.wait_group 0;" ::: "memory");
        __syncthreads();

        uint32_t kb = sb + ((uint32_t)buf << 14);
        uint32_t vb = sb + 32768u + ((uint32_t)buf << 14);

        #pragma unroll
        for (int h = 0; h < 2; h++) {
            float sf[2][8][4];
            #pragma unroll
            for (int nn_l = 0; nn_l < 8; nn_l++) {
                #pragma unroll
                for (int mt = 0; mt < 2; mt++) {
                    sf[mt][nn_l][0] = 0.f; sf[mt][nn_l][1] = 0.f;
                    sf[mt][nn_l][2] = 0.f; sf[mt][nn_l][3] = 0.f;
                }
                int nn = 8 * h + nn_l;
                #pragma unroll
                for (int kk = 0; kk < 4; kk++) {
                    uint32_t b0, b1;
                    lds64(kb + ((uint32_t)(nn * 4 + kk) << 8) + ((uint32_t)l << 3), b0, b1);
                    mma_bf16(sf[0][nn_l], qf[0][kk], b0, b1);
                    mma_bf16(sf[1][nn_l], qf[1][kk], b0, b1);
                }
            }

            #pragma unroll
            for (int mt = 0; mt < 2; mt++) {
                float s0 = 0.f, s1 = 0.f;
                #pragma unroll
                for (int nn = 0; nn < 8; nn++) {
                    sf[mt][nn][0] = ex2f(sf[mt][nn][0]);
                    sf[mt][nn][1] = ex2f(sf[mt][nn][1]);
                    sf[mt][nn][2] = ex2f(sf[mt][nn][2]);
                    sf[mt][nn][3] = ex2f(sf[mt][nn][3]);
                    s0 += sf[mt][nn][0] + sf[mt][nn][1];
                    s1 += sf[mt][nn][2] + sf[mt][nn][3];
                }
                ls[mt][0] += s0;
                ls[mt][1] += s1;
            }

            uint32_t pf[2][4][4];
            #pragma unroll
            for (int mt = 0; mt < 2; mt++)
                #pragma unroll
                for (int m = 0; m < 4; m++) {
                    pf[mt][m][0] = bf16x2(sf[mt][2*m  ][0], sf[mt][2*m  ][1]);
                    pf[mt][m][1] = bf16x2(sf[mt][2*m  ][2], sf[mt][2*m  ][3]);
                    pf[mt][m][2] = bf16x2(sf[mt][2*m+1][0], sf[mt][2*m+1][1]);
                    pf[mt][m][3] = bf16x2(sf[mt][2*m+1][2], sf[mt][2*m+1][3]);
                }

            #pragma unroll
            for (int nn = 0; nn < 8; nn++) {
                #pragma unroll
                for (int kk_l = 0; kk_l < 4; kk_l++) {
                    int kk = 4 * h + kk_l;
                    uint32_t b0, b1;
                    lds64(vb + ((uint32_t)(nn * 8 + kk) << 8) + ((uint32_t)l << 3), b0, b1);
                    mma_bf16(of[0][nn], pf[0][kk_l], b0, b1);
                    mma_bf16(of[1][nn], pf[1][kk_l], b0, b1);
                }
            }
        }

        __syncthreads();
        if (i + 2 < 16) { stage_tile(sb, b, t0 + i + 2, buf, t); cp_commit(); }
    }
    // (final __syncthreads above: all warps done with K/V smem; w_proj pack resident)

    // ---- exp-sum reduction + store ----
    #pragma unroll
    for (int mt = 0; mt < 2; mt++) {
        ls[mt][0] += __shfl_xor_sync(0xffffffffu, ls[mt][0], 1);
        ls[mt][0] += __shfl_xor_sync(0xffffffffu, ls[mt][0], 2);
        ls[mt][1] += __shfl_xor_sync(0xffffffffu, ls[mt][1], 1);
        ls[mt][1] += __shfl_xor_sync(0xffffffffu, ls[mt][1], 2);
        if (tig == 0) {
            size_t lbase = (size_t)(kh * NB + b) * HW + q0 + w * 32 + mt * 16;
            g_ls[lbase + g]     = ls[mt][0];
            g_ls[lbase + g + 8] = ls[mt][1];
        }
    }

    // ========================================================================
    // Fused epilogue: O C-frag -> bf16 A-frag (index-identical, no smem) ->
    // 64 bf16 mma against staged w_proj -> st smem -> coalesced g_po write.
    // ========================================================================
    float* st = (float*)smem;   // [64][268] = 68608B, fits below EP_WPJ=69632
    #pragma unroll
    for (int mt = 0; mt < 2; mt++) {
        uint32_t af[4][4];
        #pragma unroll
        for (int kk = 0; kk < 4; kk++) {
            af[kk][0] = bf16x2(of[mt][2*kk  ][0], of[mt][2*kk  ][1]);
            af[kk][1] = bf16x2(of[mt][2*kk  ][2], of[mt][2*kk  ][3]);
            af[kk][2] = bf16x2(of[mt][2*kk+1][0], of[mt][2*kk+1][1]);
            af[kk][3] = bf16x2(of[mt][2*kk+1][2], of[mt][2*kk+1][3]);
        }
        int nbase = w * 32 + mt * 16 + g;
        #pragma unroll
        for (int nn = 0; nn < 8; nn++) {
            float acc[4] = {0.f, 0.f, 0.f, 0.f};
            #pragma unroll
            for (int kk = 0; kk < 4; kk++) {
                uint32_t b0, b1;
                lds64(sb + EP_WPJ + (uint32_t)((nn * 4 + kk) * 256) + (uint32_t)l * 8, b0, b1);
                mma_bf16(acc, af[kk], b0, b1);
            }
            int o = nn * 8 + 2 * tig;
            st[o * 268 + nbase]           = acc[0];
            st[(o + 1) * 268 + nbase]     = acc[1];
            st[o * 268 + nbase + 8]       = acc[2];
            st[(o + 1) * 268 + nbase + 8] = acc[3];
        }
    }
    __syncthreads();

    // coalesced write: 64 o-rows x 256 tokens
    for (int i = t; i < 4096; i += 256) {
        int o = i >> 6, f4 = i & 63;
        float4 v = *(const float4*)(st + o * 268 + f4 * 4);
        *(float4*)(g_po + (((size_t)(kh * NB + b) * 64 + o) << 12) + q0 + f4 * 4) = v;
    }
}

// ===========================================================================
// Kernel 4: elementwise merge: out = x + bias[o] + (p0+p1) * (1/(l0+l1)).
// Grid (64, NB) = 256 blocks, 512 threads; block = 64 tokens x 64 o
// = 1024 float4 -> 2 iterations of 512 threads.
// ===========================================================================
__global__ __launch_bounds__(512) void merge_kernel(
        const float* __restrict__ x,
        const float* __restrict__ b_proj,
        float* __restrict__ out) {
    __shared__ float lsinv[64];
    __shared__ float bias_s[64];
    int b  = blockIdx.y;
    int n0 = blockIdx.x << 6;
    int t = threadIdx.x;

    if (t < 64) {
        lsinv[t] = __fdividef(1.f, g_ls[(size_t)b * HW + n0 + t] +
                                   g_ls[(size_t)(NB + b) * HW + n0 + t]);
        bias_s[t] = b_proj[t];
    }
    __syncthreads();

    #pragma unroll
    for (int j = 0; j < 2; j++) {
        int idx = j * 512 + t;           // 0..1023 float4s
        int o = idx >> 4, f4 = idx & 15; // o < 64, 16 float4 per 64-token row
        size_t e0 = (((size_t)(b * 64 + o)) << 12) + n0 + f4 * 4;
        float4 a  = *(const float4*)(g_po + e0);
        float4 c  = *(const float4*)(g_po + (((size_t)(NB * 64) << 12)) + e0);
        float4 xv = *(const float4*)(x + e0);
        int nb4 = f4 * 4;
        float bias = bias_s[o];
        float4 r;
        r.x = xv.x + bias + (a.x + c.x) * lsinv[nb4    ];
        r.y = xv.y + bias + (a.y + c.y) * lsinv[nb4 + 1];
        r.z = xv.z + bias + (a.z + c.z) * lsinv[nb4 + 2];
        r.w = xv.w + bias + (a.w + c.w) * lsinv[nb4 + 3];
        *(float4*)(out + e0) = r;
    }
}

// ===========================================================================
extern "C" void kernel_launch(void* const* d_in, const int* in_sizes, int n_in,
                              void* d_out, int out_size) {
    const float* x      = (const float*)d_in[0];
    const float* w_qkv  = (const float*)d_in[1];
    const float* b_qkv  = (const float*)d_in[2];
    const float* w_proj = (const float*)d_in[3];
    const float* b_proj = (const float*)d_in[4];
    float* out = (float*)d_out;

    cudaFuncSetAttribute(qkv_kernel,
                         cudaFuncAttributeMaxDynamicSharedMemorySize, QKV2_SMEM);
    cudaFuncSetAttribute(attn_mma_kernel,
                         cudaFuncAttributeMaxDynamicSharedMemorySize, SMEM_ATT);

    stats_kernel<<<BC*4, 128>>>(x, w_qkv, w_proj);
    qkv_kernel<<<dim3(64, NB), 256, QKV2_SMEM>>>(x, b_qkv);
    attn_mma_kernel<<<dim3(32, NB), 256, SMEM_ATT>>>();
    merge_kernel<<<dim3(64, NB), 512>>>(x, b_proj, out);
}